// round 10
// baseline (speedup 1.0000x reference)
#include <cuda_runtime.h>

#define NN    100000
#define EE    1600000
#define HID   64
#define HID2  128
#define EDIM  16
#define INDIM 32

// ---------------- scratch (device globals; no allocation) ----------------
__device__ float  g_hA[NN * HID];
__device__ float  g_hB[NN * HID];
__device__ float  g_tmp[NN * HID];
__device__ int    g_deg[NN];
__device__ int    g_cnt[NN];
__device__ int    g_rowptr[NN + 1];
__device__ int    g_blksum[256];
__device__ int    g_srcp[EE];          // src index permuted to CSR order
__device__ float4 g_eap[EE * 4];       // edge_attr permuted to CSR order (64 B/edge)

// ---------------- CSR build ----------------
__global__ void k_zero(int N) {
    int i = blockIdx.x * blockDim.x + threadIdx.x;
    if (i < N) { g_deg[i] = 0; g_cnt[i] = 0; }
}

__global__ void k_hist(const int* __restrict__ dst, int E) {
    int e = blockIdx.x * blockDim.x + threadIdx.x;
    if (e < E) atomicAdd(&g_deg[dst[e]], 1);
}

__global__ void k_scan1(int N) {
    __shared__ int sh[1024];
    int i = blockIdx.x * 1024 + threadIdx.x;
    int v = (i < N) ? g_deg[i] : 0;
    sh[threadIdx.x] = v;
    __syncthreads();
    for (int off = 1; off < 1024; off <<= 1) {
        int add = (threadIdx.x >= off) ? sh[threadIdx.x - off] : 0;
        __syncthreads();
        sh[threadIdx.x] += add;
        __syncthreads();
    }
    if (i < N) g_rowptr[i] = sh[threadIdx.x] - v;     // exclusive
    if (threadIdx.x == 1023) g_blksum[blockIdx.x] = sh[1023];
}

__global__ void k_scan2(int B) {
    if (blockIdx.x == 0 && threadIdx.x == 0) {
        int acc = 0;
        for (int b = 0; b < B; b++) { int t = g_blksum[b]; g_blksum[b] = acc; acc += t; }
    }
}

__global__ void k_scan3(int N, int E) {
    int i = blockIdx.x * 1024 + threadIdx.x;
    if (i < N) g_rowptr[i] += g_blksum[blockIdx.x];
    if (i == 0) g_rowptr[N] = E;
}

// scatter: build CSR-permuted src and edge_attr streams
__global__ void k_scatter(const int* __restrict__ src, const int* __restrict__ dst,
                          const float4* __restrict__ ea, int E) {
    int e = blockIdx.x * blockDim.x + threadIdx.x;
    if (e >= E) return;
    int d = dst[e];
    int p = g_rowptr[d] + atomicAdd(&g_cnt[d], 1);
    g_srcp[p] = src[e];
    float4 a0 = __ldg(ea + e * 4 + 0);
    float4 a1 = __ldg(ea + e * 4 + 1);
    float4 a2 = __ldg(ea + e * 4 + 2);
    float4 a3 = __ldg(ea + e * 4 + 3);
    g_eap[p * 4 + 0] = a0;
    g_eap[p * 4 + 1] = a1;
    g_eap[p * 4 + 2] = a2;
    g_eap[p * 4 + 3] = a3;
}

// ---------------- input linear: h = x @ src_w + src_b ----------------
__global__ void k_inlin(const float* __restrict__ x, const float* __restrict__ w,
                        const float* __restrict__ b, int N) {
    int idx = blockIdx.x * blockDim.x + threadIdx.x;
    if (idx >= N * HID) return;
    int n = idx >> 6, c = idx & 63;
    const float* xr = x + n * INDIM;
    float acc = __ldg(&b[c]);
#pragma unroll
    for (int k = 0; k < INDIM; k++)
        acc = fmaf(__ldg(&xr[k]), __ldg(&w[k * HID + c]), acc);
    g_hA[idx] = acc;
}

// ---------------- aggregation: warp-per-node, 8-edge software pipeline -------
// dir=0: read g_hA; dir=1: read g_hB. Writes g_tmp.
// lane owns channels (2*lane, 2*lane+1).
__device__ __forceinline__ void agg_edge(
    float2 h, const float4* __restrict__ ea, const float2* __restrict__ ewr,
    float eb0, float eb1, float& s0, float& s1, float& t0, float& t1)
{
    float4 a0 = __ldg(ea + 0), a1 = __ldg(ea + 1);
    float4 a2 = __ldg(ea + 2), a3 = __ldg(ea + 3);
    float av[16] = {a0.x, a0.y, a0.z, a0.w, a1.x, a1.y, a1.z, a1.w,
                    a2.x, a2.y, a2.z, a2.w, a3.x, a3.y, a3.z, a3.w};
    float v0 = eb0, v1 = eb1;
#pragma unroll
    for (int k = 0; k < EDIM; k++) {
        v0 = fmaf(av[k], ewr[k].x, v0);
        v1 = fmaf(av[k], ewr[k].y, v1);
    }
    // msg = relu(h+v); eps added at the end (softmax shift-invariant).
    // No max-subtraction: msg >= 0 and O(10) -> expf cannot overflow.
    float r0 = fmaxf(h.x + v0, 0.f);
    float r1 = fmaxf(h.y + v1, 0.f);
    float w0 = __expf(r0);
    float w1 = __expf(r1);
    s0 += w0;
    s1 += w1;
    t0 = fmaf(r0, w0, t0);
    t1 = fmaf(r1, w1, t1);
}

__global__ void __launch_bounds__(256)
k_agg(int dir, const float* __restrict__ ew, const float* __restrict__ ebias, int N) {
    const float* hin = dir ? g_hB : g_hA;
    int warp = threadIdx.x >> 5, lane = threadIdx.x & 31;
    int n = blockIdx.x * 8 + warp;
    if (n >= N) return;

    // preload ew columns for this lane's two channels
    float2 ewr[EDIM];
#pragma unroll
    for (int k = 0; k < EDIM; k++)
        ewr[k] = __ldg((const float2*)(ew + k * HID) + lane);
    float2 eb = __ldg((const float2*)ebias + lane);
    float2 hs = __ldg((const float2*)(hin + n * HID) + lane);   // self feature, hoisted

    int beg = g_rowptr[n], end = g_rowptr[n + 1];
    float s0 = 0.f, s1 = 0.f, t0 = 0.f, t1 = 0.f;

    int i = beg;
    // scalar prologue to reach 16B alignment of srcp
    for (; i < end && (i & 3); i++) {
        int sv = __ldg(&g_srcp[i]);
        float2 h = __ldg((const float2*)(hin + sv * HID) + lane);
        agg_edge(h, g_eap + (size_t)i * 4, ewr, eb.x, eb.y, s0, s1, t0, t1);
    }
    // 8-edge pipelined main loop: 2x int4 src loads + 8 h-gathers batched
    for (; i + 8 <= end; i += 8) {
        int4 svA = __ldg((const int4*)(g_srcp + i));
        int4 svB = __ldg((const int4*)(g_srcp + i + 4));
        float2 h0 = __ldg((const float2*)(hin + svA.x * HID) + lane);
        float2 h1 = __ldg((const float2*)(hin + svA.y * HID) + lane);
        float2 h2 = __ldg((const float2*)(hin + svA.z * HID) + lane);
        float2 h3 = __ldg((const float2*)(hin + svA.w * HID) + lane);
        float2 h4 = __ldg((const float2*)(hin + svB.x * HID) + lane);
        float2 h5 = __ldg((const float2*)(hin + svB.y * HID) + lane);
        float2 h6 = __ldg((const float2*)(hin + svB.z * HID) + lane);
        float2 h7 = __ldg((const float2*)(hin + svB.w * HID) + lane);
        agg_edge(h0, g_eap + (size_t)(i + 0) * 4, ewr, eb.x, eb.y, s0, s1, t0, t1);
        agg_edge(h1, g_eap + (size_t)(i + 1) * 4, ewr, eb.x, eb.y, s0, s1, t0, t1);
        agg_edge(h2, g_eap + (size_t)(i + 2) * 4, ewr, eb.x, eb.y, s0, s1, t0, t1);
        agg_edge(h3, g_eap + (size_t)(i + 3) * 4, ewr, eb.x, eb.y, s0, s1, t0, t1);
        agg_edge(h4, g_eap + (size_t)(i + 4) * 4, ewr, eb.x, eb.y, s0, s1, t0, t1);
        agg_edge(h5, g_eap + (size_t)(i + 5) * 4, ewr, eb.x, eb.y, s0, s1, t0, t1);
        agg_edge(h6, g_eap + (size_t)(i + 6) * 4, ewr, eb.x, eb.y, s0, s1, t0, t1);
        agg_edge(h7, g_eap + (size_t)(i + 7) * 4, ewr, eb.x, eb.y, s0, s1, t0, t1);
    }
    // 4-edge tail
    for (; i + 4 <= end; i += 4) {
        int4 sv = __ldg((const int4*)(g_srcp + i));
        float2 h0 = __ldg((const float2*)(hin + sv.x * HID) + lane);
        float2 h1 = __ldg((const float2*)(hin + sv.y * HID) + lane);
        float2 h2 = __ldg((const float2*)(hin + sv.z * HID) + lane);
        float2 h3 = __ldg((const float2*)(hin + sv.w * HID) + lane);
        agg_edge(h0, g_eap + (size_t)(i + 0) * 4, ewr, eb.x, eb.y, s0, s1, t0, t1);
        agg_edge(h1, g_eap + (size_t)(i + 1) * 4, ewr, eb.x, eb.y, s0, s1, t0, t1);
        agg_edge(h2, g_eap + (size_t)(i + 2) * 4, ewr, eb.x, eb.y, s0, s1, t0, t1);
        agg_edge(h3, g_eap + (size_t)(i + 3) * 4, ewr, eb.x, eb.y, s0, s1, t0, t1);
    }
    // scalar tail
    for (; i < end; i++) {
        int sv = __ldg(&g_srcp[i]);
        float2 h = __ldg((const float2*)(hin + sv * HID) + lane);
        agg_edge(h, g_eap + (size_t)i * 4, ewr, eb.x, eb.y, s0, s1, t0, t1);
    }

    float o0 = (s0 > 0.f ? __fdividef(t0, s0) + 1e-7f : 0.f) + hs.x;
    float o1 = (s1 > 0.f ? __fdividef(t1, s1) + 1e-7f : 0.f) + hs.y;
    *((float2*)(g_tmp + n * HID) + lane) = make_float2(o0, o1);
}

// ---------------- MLP: Linear(64->128) -> BN -> ReLU -> Linear(128->64) -> ReLU
// reads g_tmp; dir=0: write g_hB; dir=1: write g_hA.
// 32 nodes per block, 256 threads, register-tiled, float4 LDS
__global__ void __launch_bounds__(256)
k_mlp(int dir,
      const float* __restrict__ w1, const float* __restrict__ b1,
      const float* __restrict__ gam, const float* __restrict__ bet,
      const float* __restrict__ w2, const float* __restrict__ b2, int N) {
    float* outp = dir ? g_hA : g_hB;
    __shared__ float s_in[32][HID];     // 8 KB
    __shared__ float s_hh[32][HID2];    // 16 KB
    int tid = threadIdx.x;
    int base = blockIdx.x * 32;

    // stage 32 node rows (zero-fill past N)
    {
        const float4* src4 = (const float4*)(g_tmp + base * HID);
        float4* dst4 = (float4*)&s_in[0][0];
        long limit4 = (long)(N - base) * (HID / 4);
#pragma unroll
        for (int t = 0; t < 2; t++) {
            int i = tid + t * 256;
            dst4[i] = (i < limit4) ? __ldg(src4 + i) : make_float4(0.f, 0.f, 0.f, 0.f);
        }
    }
    __syncthreads();

    // phase 1: hh = relu(BN(in @ w1 + b1)); thread: 8 nodes x 2 adjacent j
    {
        int jp  = tid & 63;
        int grp = tid >> 6;
        float2 bb = __ldg((const float2*)b1 + jp);
        float a0[8], a1[8];
#pragma unroll
        for (int u = 0; u < 8; u++) { a0[u] = bb.x; a1[u] = bb.y; }
#pragma unroll
        for (int k4 = 0; k4 < HID; k4 += 4) {
            float2 w0 = __ldg((const float2*)(w1 + (k4 + 0) * HID2) + jp);
            float2 w1v = __ldg((const float2*)(w1 + (k4 + 1) * HID2) + jp);
            float2 w2v = __ldg((const float2*)(w1 + (k4 + 2) * HID2) + jp);
            float2 w3 = __ldg((const float2*)(w1 + (k4 + 3) * HID2) + jp);
#pragma unroll
            for (int u = 0; u < 8; u++) {
                float4 xv = *(const float4*)&s_in[grp * 8 + u][k4];
                a0[u] = fmaf(xv.x, w0.x, a0[u]);
                a1[u] = fmaf(xv.x, w0.y, a1[u]);
                a0[u] = fmaf(xv.y, w1v.x, a0[u]);
                a1[u] = fmaf(xv.y, w1v.y, a1[u]);
                a0[u] = fmaf(xv.z, w2v.x, a0[u]);
                a1[u] = fmaf(xv.z, w2v.y, a1[u]);
                a0[u] = fmaf(xv.w, w3.x, a0[u]);
                a1[u] = fmaf(xv.w, w3.y, a1[u]);
            }
        }
        const float BNC = 0.9999950000375f;    // 1/sqrt(1+1e-5)
        float2 gm = __ldg((const float2*)gam + jp);
        float2 bt = __ldg((const float2*)bet + jp);
        float g0 = gm.x * BNC, g1 = gm.y * BNC;
#pragma unroll
        for (int u = 0; u < 8; u++) {
            float2 hv;
            hv.x = fmaxf(fmaf(a0[u], g0, bt.x), 0.f);
            hv.y = fmaxf(fmaf(a1[u], g1, bt.y), 0.f);
            *((float2*)&s_hh[grp * 8 + u][0] + jp) = hv;
        }
    }
    __syncthreads();

    // phase 2: y = relu(hh @ w2 + b2); thread: 4 nodes x 2 adjacent c
    {
        int cp  = tid & 31;
        int grp = tid >> 5;
        float2 bb = __ldg((const float2*)b2 + cp);
        float a0[4], a1[4];
#pragma unroll
        for (int u = 0; u < 4; u++) { a0[u] = bb.x; a1[u] = bb.y; }
#pragma unroll
        for (int k4 = 0; k4 < HID2; k4 += 4) {
            float2 w0 = __ldg((const float2*)(w2 + (k4 + 0) * HID) + cp);
            float2 w1v = __ldg((const float2*)(w2 + (k4 + 1) * HID) + cp);
            float2 w2v = __ldg((const float2*)(w2 + (k4 + 2) * HID) + cp);
            float2 w3 = __ldg((const float2*)(w2 + (k4 + 3) * HID) + cp);
#pragma unroll
            for (int u = 0; u < 4; u++) {
                float4 xv = *(const float4*)&s_hh[grp * 4 + u][k4];
                a0[u] = fmaf(xv.x, w0.x, a0[u]);
                a1[u] = fmaf(xv.x, w0.y, a1[u]);
                a0[u] = fmaf(xv.y, w1v.x, a0[u]);
                a1[u] = fmaf(xv.y, w1v.y, a1[u]);
                a0[u] = fmaf(xv.z, w2v.x, a0[u]);
                a1[u] = fmaf(xv.z, w2v.y, a1[u]);
                a0[u] = fmaf(xv.w, w3.x, a0[u]);
                a1[u] = fmaf(xv.w, w3.y, a1[u]);
            }
        }
#pragma unroll
        for (int u = 0; u < 4; u++) {
            int node = base + grp * 4 + u;
            if (node < N) {
                float2 ov;
                ov.x = fmaxf(a0[u], 0.f);   // outer relu
                ov.y = fmaxf(a1[u], 0.f);
                *((float2*)(outp + node * HID) + cp) = ov;
            }
        }
    }
}

// ---------------- head ----------------
__global__ void k_head(const float* __restrict__ gfeat, const int* __restrict__ ngp,
                       const float* __restrict__ hw, const float* __restrict__ hb,
                       float* __restrict__ out, int N, int gfd) {
    int n = blockIdx.x * blockDim.x + threadIdx.x;
    if (n >= N) return;
    const float* h = g_hA;   // final features land in A (A->B->A)
    float acc = __ldg(&hb[0]);
#pragma unroll 8
    for (int c = 0; c < HID; c++)
        acc = fmaf(h[n * HID + c], __ldg(&hw[c]), acc);
    int G = *ngp;
    int npg = N / G;
    int g = n / npg, r = n - g * npg;
    for (int d = 0; d < gfd; d++)
        acc = fmaf(__ldg(&gfeat[(g * gfd + d) * npg + r]), __ldg(&hw[HID + d]), acc);
    out[n] = acc;
}

// ---------------- launch ----------------
extern "C" void kernel_launch(void* const* d_in, const int* in_sizes, int n_in,
                              void* d_out, int out_size) {
    const float* x     = (const float*)d_in[0];
    const int*   eidx  = (const int*)d_in[1];
    const float* eattr = (const float*)d_in[2];
    const int*   ngp   = (const int*)d_in[3];
    const float* gfeat = (const float*)d_in[4];
    const float* src_w = (const float*)d_in[5];
    const float* src_b = (const float*)d_in[6];

    int N   = in_sizes[0] / INDIM;
    int E   = in_sizes[1] / 2;
    int gfd = in_sizes[4] / N;

    const int* src = eidx;
    const int* dst = eidx + E;

    // CSR build + permuted edge streams
    k_zero<<<(N + 255) / 256, 256>>>(N);
    k_hist<<<(E + 255) / 256, 256>>>(dst, E);
    int nb = (N + 1023) / 1024;
    k_scan1<<<nb, 1024>>>(N);
    k_scan2<<<1, 32>>>(nb);
    k_scan3<<<nb, 1024>>>(N, E);
    k_scatter<<<(E + 255) / 256, 256>>>(src, dst, (const float4*)eattr, E);

    // h0 = x @ src_w + src_b   (writes g_hA)
    k_inlin<<<(N * HID + 255) / 256, 256>>>(x, src_w, src_b, N);

    // layer 0: hA -> tmp -> hB
    k_agg<<<(N + 7) / 8, 256>>>(0, (const float*)d_in[7], (const float*)d_in[8], N);
    k_mlp<<<(N + 31) / 32, 256>>>(0,
        (const float*)d_in[9],  (const float*)d_in[10],
        (const float*)d_in[11], (const float*)d_in[12],
        (const float*)d_in[13], (const float*)d_in[14], N);

    // layer 1: hB -> tmp -> hA
    k_agg<<<(N + 7) / 8, 256>>>(1, (const float*)d_in[15], (const float*)d_in[16], N);
    k_mlp<<<(N + 31) / 32, 256>>>(1,
        (const float*)d_in[17], (const float*)d_in[18],
        (const float*)d_in[19], (const float*)d_in[20],
        (const float*)d_in[21], (const float*)d_in[22], N);

    // head
    k_head<<<(N + 255) / 256, 256>>>(gfeat, ngp,
        (const float*)d_in[23], (const float*)d_in[24],
        (float*)d_out, N, gfd);
    (void)n_in; (void)out_size;
}